// round 13
// baseline (speedup 1.0000x reference)
#include <cuda_runtime.h>

#define NMAX  100000
#define EMAX  3200000
#define NF    512
#define NH    8
#define NC    16

// ---------------- scratch (no allocations allowed) ----------------
__device__ float g_s1[NMAX * NH];          // x @ W1 (pre-spmm)
__device__ float g_xr[NMAX * NH];          // affine(relu(bi-interaction))
__device__ float g_s2[NMAX * NC];          // h @ W2
__device__ int   g_cnt[NMAX];              // per-row degree
__device__ int   g_offs[NMAX];             // CSR row range start (arbitrary order)
__device__ int   g_cur[NMAX];              // scatter cursors
__device__ int   g_total;                  // global range allocator
__device__ unsigned long long g_ep[EMAX];  // packed edges: lo=col, hi=val bits

typedef unsigned long long u64;

// ---------------- f32x2 helpers (FFMA2 = full-rate fp32 on sm_103a) ---
#define UNPACK2(lo, hi, in) \
    asm("mov.b64 {%0, %1}, %2;" : "=f"(lo), "=f"(hi) : "l"(in))
#define MUL2(out, a, b) \
    asm("mul.rn.f32x2 %0, %1, %2;" : "=l"(out) : "l"(a), "l"(b))
#define FMA2(acc, a, b) \
    asm("fma.rn.f32x2 %0, %1, %2, %0;" : "+l"(acc) : "l"(a), "l"(b))

// =====================================================================
// launch 0: zero counters
// =====================================================================
__global__ void k_zero(int n) {
    int i = blockIdx.x * blockDim.x + threadIdx.x;
    int i4 = i * 4;
    if (i4 + 3 < n) {
        *(int4*)(g_cnt + i4) = make_int4(0, 0, 0, 0);
    } else {
        for (int q = 0; q < 4; q++) if (i4 + q < n) g_cnt[i4 + q] = 0;
    }
    if (i == 0) g_total = 0;
}

// =====================================================================
// launch 1: degree histogram
// =====================================================================
__global__ void k_hist(const int* __restrict__ rows, int e) {
    int i = blockIdx.x * blockDim.x + threadIdx.x;
    if (i < e) atomicAdd(&g_cnt[rows[i]], 1);
}

// =====================================================================
// launch 2: allocate contiguous per-row ranges (block scan + 1 atomic/block)
// =====================================================================
__global__ void __launch_bounds__(256) k_alloc(int n) {
    __shared__ int wsum[8];
    __shared__ int wpref[8];
    __shared__ int blockBase;
    int t = threadIdx.x;
    int lane = t & 31, wid = t >> 5;
    int base = blockIdx.x * 1024 + t * 4;

    int v[4]; int s = 0;
#pragma unroll
    for (int q = 0; q < 4; q++) { int i = base + q; v[q] = (i < n) ? g_cnt[i] : 0; s += v[q]; }

    int sc = s;
#pragma unroll
    for (int d = 1; d < 32; d <<= 1) {
        int u = __shfl_up_sync(~0u, sc, d);
        if (lane >= d) sc += u;
    }
    if (lane == 31) wsum[wid] = sc;
    __syncthreads();
    if (t == 0) {
        int run = 0;
#pragma unroll
        for (int w = 0; w < 8; w++) { wpref[w] = run; run += wsum[w]; }
        blockBase = atomicAdd(&g_total, run);
    }
    __syncthreads();

    int run = blockBase + wpref[wid] + (sc - s);
#pragma unroll
    for (int q = 0; q < 4; q++) {
        int i = base + q;
        if (i < n) {
            g_offs[i] = run;
            g_cur[i]  = run;
            run += v[q];
        }
    }
}

// =====================================================================
// launch 3 (PROFILED SLOT): gemmA v8 — warp h-split for occupancy
// 256 threads / block, 256-node tile staged ONCE in smem.
// Thread t: node = nb + (t & 127), h-group = t >> 7 (4 h's each).
// 12 u64 accumulators/thread (~75 regs) -> 3 blocks/SM = 24 warps/SM.
// Same aggregate pipe load as v7, double the latency hiding.
// =====================================================================
#define TILEN  256
#define KCHUNK 16
#define XPITCH 20   // 16 + 4 pad: 16B-aligned

__global__ void __launch_bounds__(256, 3) k_gemmA(
    const float* __restrict__ x, const float* __restrict__ W1,
    const float* __restrict__ V, const float* __restrict__ gamma,
    const float* __restrict__ beta, int n)
{
    extern __shared__ float sm[];
    float* wT = sm;                    // [3*8][512]  48 KB
    float* xs = sm + 3 * NH * NF;      // [256][20]   20 KB
    const int t = threadIdx.x;
    const int nb = blockIdx.x * TILEN;
    const int nrow  = t & 127;         // node row within tile half
    const int hbase = (t >> 7) * 4;    // 0 or 4 — uniform per warp

    // stage combined weights once per block, transposed to [mat][h][k]
    for (int i = t; i < NF * NH; i += 256) {
        int k = i >> 3, h = i & 7;
        float a = W1[i];
        float b = V[i];
        wT[h * NF + k]             = a;
        wT[(NH + h) * NF + k]      = b;
        wT[(2 * NH + h) * NF + k]  = b * b;
    }

    u64 a1[4], av[4], a2[4];
#pragma unroll
    for (int h = 0; h < 4; h++) { a1[h] = 0ull; av[h] = 0ull; a2[h] = 0ull; }

    for (int kc = 0; kc < NF; kc += KCHUNK) {
        __syncthreads();
        // stage x chunk [256 nodes][16 k]: 1024 float4 over 256 threads
#pragma unroll
        for (int q = 0; q < 4; q++) {
            int idx = t + 256 * q;
            int row = idx >> 2, f = idx & 3;
            int gn = nb + row;
            float4 val = make_float4(0.f, 0.f, 0.f, 0.f);
            if (gn < n) val = *(const float4*)(x + (size_t)gn * NF + kc + f * 4);
            *(float4*)(xs + row * XPITCH + f * 4) = val;
        }
        __syncthreads();

        // this thread's node row lives at xs[nrow + 128*(t>>7)]? No:
        // both h-groups cover ALL 256 nodes: group0 -> nodes 0..127,
        // group1 -> nodes 128..255 for h4-7?  WRONG — each node needs all 8 h.
        // Correct mapping: node index = nrow + (hbase ? 0 : 0) ... see below.
        // Each node processed by TWO threads: t and t+128 (same nrow),
        // one per h-group. Lower half nodes: nrow in 0..127 -> node nb+nrow.
        // Upper half nodes (128..255) handled by SECOND pass below.
#pragma unroll
        for (int half = 0; half < 2; half++) {
            const float* xrow = xs + (nrow + half * 128) * XPITCH;
#pragma unroll
            for (int kk = 0; kk < KCHUNK; kk += 4) {
                ulonglong2 xp = *(const ulonglong2*)(xrow + kk);
                u64 sA, sB;
                MUL2(sA, xp.x, xp.x);
                MUL2(sB, xp.y, xp.y);
                const float* wb = wT + kc + kk;
#pragma unroll
                for (int h = 0; h < 2; h++) {
                    int gh = hbase + half * 2 + h;   // uniform per warp
                    ulonglong2 w1p = *(const ulonglong2*)(wb + gh * NF);
                    ulonglong2 wvp = *(const ulonglong2*)(wb + (NH + gh) * NF);
                    ulonglong2 w2p = *(const ulonglong2*)(wb + (2 * NH + gh) * NF);
                    int a = half * 2 + h;
                    FMA2(a1[a], xp.x, w1p.x); FMA2(a1[a], xp.y, w1p.y);
                    FMA2(av[a], xp.x, wvp.x); FMA2(av[a], xp.y, wvp.y);
                    FMA2(a2[a], sA,   w2p.x); FMA2(a2[a], sB,   w2p.y);
                }
            }
        }
    }

    // epilogue: thread t wrote, for half=0: node nb+nrow, h = hbase..hbase+1
    //                        for half=1: node nb+nrow+128, h = hbase+2..hbase+3
    // Wait — that means each (node,h) pair is covered exactly once:
    //   node in lower half gets h {hbase, hbase+1} from both hgroups = {0,1,4,5}
    //   node in upper half gets {2,3,6,7}.  INCONSISTENT per node!
    // Fix: write outputs exactly as accumulated — lower-half nodes get
    // h columns {0,1} from group0-threads and {4,5} from group1-threads;
    // upper-half nodes get {2,3} and {6,7}. That's only 4 of 8 h per node!
    // => swap: for half=1 use SAME h as half=0 but those are different accs.
    // Resolution below: we accumulated a[0..1] for node lo with gh=hbase+0..1
    // and a[2..3] for node hi with gh=hbase+2..3. To cover all h for all
    // nodes, the OTHER h's of node lo (hbase+2..3) must come from... nobody.
    // --> Use 4 h per node per thread via half-loop over h instead of nodes:
    //     (corrected accumulation below replaced this comment block's logic)
    {
#pragma unroll
        for (int half = 0; half < 2; half++) {
            int node = nb + nrow + half * 128;
            if (node < n) {
                float s1o[2], xro[2];
#pragma unroll
                for (int h = 0; h < 2; h++) {
                    int gh = hbase + half * 2 + h;
                    int a = half * 2 + h;
                    float l0, l1;
                    UNPACK2(l0, l1, a1[a]); s1o[h] = l0 + l1;
                    UNPACK2(l0, l1, av[a]); float xv   = l0 + l1;
                    UNPACK2(l0, l1, a2[a]); float x2v2 = l0 + l1;
                    float r = 0.5f * (xv * xv - x2v2);
                    r = r > 0.f ? r : 0.f;
                    xro[h] = gamma[gh] * r + beta[gh];
                }
                int gh0 = hbase + half * 2;
                *(float2*)(g_s1 + (size_t)node * NH + gh0) = make_float2(s1o[0], s1o[1]);
                *(float2*)(g_xr + (size_t)node * NH + gh0) = make_float2(xro[0], xro[1]);
            }
        }
    }
}

// NOTE on coverage: thread (nrow, hg) with half-loop covers
//   (node lo , h = hg*4 + 0..1)  and  (node hi , h = hg*4 + 2..3).
// Thread (nrow, other hg) covers (node lo, other*4 + 0..1), (node hi, other*4+2..3).
// So node lo receives h {0,1,4,5} and node hi receives h {2,3,6,7} — HALF MISSING.
// The kernel above is therefore WRONG as-is; the corrected version maps
// half to the H-PAIR instead of the node:
//   half=0: node lo, h pair {hbase+0,hbase+1}
//   half=1: node lo, h pair {hbase+2,hbase+3}   (same node, all 4 h!)
// and upper-half nodes are handled by... no thread. 128 threads * 2 hgroups
// cover 128 nodes * 8 h. TILEN must be 128 for full coverage.
// The launcher below uses TILEN_EFF = 128 via grid doubling and the
// `nb` derivation handles it: see k_gemmA_fixed.

__global__ void __launch_bounds__(256, 3) k_gemmA_fixed(
    const float* __restrict__ x, const float* __restrict__ W1,
    const float* __restrict__ V, const float* __restrict__ gamma,
    const float* __restrict__ beta, int n)
{
    extern __shared__ float sm[];
    float* wT = sm;                    // [3*8][512]  48 KB
    float* xs = sm + 3 * NH * NF;      // [256][20]   20 KB
    const int t = threadIdx.x;
    const int nb = blockIdx.x * TILEN;     // 256-node tile
    const int nrow  = t & 127;
    const int hbase = (t >> 7) * 4;        // uniform per warp

    for (int i = t; i < NF * NH; i += 256) {
        int k = i >> 3, h = i & 7;
        float a = W1[i];
        float b = V[i];
        wT[h * NF + k]             = a;
        wT[(NH + h) * NF + k]      = b;
        wT[(2 * NH + h) * NF + k]  = b * b;
    }

    // accumulators: [node-half][h-pair within group of 4]
    u64 a1[2][2], av[2][2], a2[2][2];
#pragma unroll
    for (int nd = 0; nd < 2; nd++)
#pragma unroll
        for (int h = 0; h < 2; h++) { a1[nd][h] = 0ull; av[nd][h] = 0ull; a2[nd][h] = 0ull; }
    // coverage: thread handles node lo = nb+nrow and node hi = nb+nrow+128,
    // each with 2 of its group's 4 h's?? Still half. -> Use 2 h per node from
    // THIS group; the other 2 h of the group for these nodes come from the
    // PAIRED k-iteration: we simply do all 4 h for both nodes = 24 accs. Too
    // many regs. FINAL CHOICE: 4 h x 1 node (node = nb2 + t, 256-node tile,
    // where tile spans the full 256 threads and each node is visited by both
    // h-groups at the same nrow? t&127 collides for t and t+128.
    // Simplest correct low-reg mapping: TILE = 128 nodes, node = nb128 + (t&127),
    // thread computes its group's 4 h's for that node: 12 accs = 24 regs. Both
    // h-groups cover the same 128 nodes. x staged once (128 rows). Done below.
    (void)nb; (void)nrow; (void)hbase;
}

// =====================================================================
// FINAL gemmA v8: 128-node tile, 256 threads.
// node = nb + (t & 127); h-group = (t>>7)*4; 4 h x 3 mats = 12 u64 accs.
// Both warpsets read the same 128-row x tile (staged once, 10 KB).
// smem = 48 KB wT + 10 KB x = 58 KB -> 3 blocks/SM, 24 warps/SM.
// =====================================================================
#define XTILE 128

__global__ void __launch_bounds__(256, 3) k_gemmA_v8(
    const float* __restrict__ x, const float* __restrict__ W1,
    const float* __restrict__ V, const float* __restrict__ gamma,
    const float* __restrict__ beta, int n)
{
    extern __shared__ float sm[];
    float* wT = sm;                    // [3*8][512]  48 KB
    float* xs = sm + 3 * NH * NF;      // [128][20]   10 KB
    const int t = threadIdx.x;
    const int nb = blockIdx.x * XTILE;
    const int nrow  = t & 127;
    const int hbase = (t >> 7) * 4;    // 0 or 4 — uniform per warp

    for (int i = t; i < NF * NH; i += 256) {
        int k = i >> 3, h = i & 7;
        float a = W1[i];
        float b = V[i];
        wT[h * NF + k]             = a;
        wT[(NH + h) * NF + k]      = b;
        wT[(2 * NH + h) * NF + k]  = b * b;
    }

    u64 a1[4], av[4], a2[4];
#pragma unroll
    for (int h = 0; h < 4; h++) { a1[h] = 0ull; av[h] = 0ull; a2[h] = 0ull; }

    for (int kc = 0; kc < NF; kc += KCHUNK) {
        __syncthreads();
        // stage x chunk [128 nodes][16 k]: 512 float4 over 256 threads
#pragma unroll
        for (int q = 0; q < 2; q++) {
            int idx = t + 256 * q;
            int row = idx >> 2, f = idx & 3;
            int gn = nb + row;
            float4 val = make_float4(0.f, 0.f, 0.f, 0.f);
            if (gn < n) val = *(const float4*)(x + (size_t)gn * NF + kc + f * 4);
            *(float4*)(xs + row * XPITCH + f * 4) = val;
        }
        __syncthreads();

        const float* xrow = xs + nrow * XPITCH;
#pragma unroll
        for (int kk = 0; kk < KCHUNK; kk += 4) {
            ulonglong2 xp = *(const ulonglong2*)(xrow + kk);
            u64 sA, sB;
            MUL2(sA, xp.x, xp.x);
            MUL2(sB, xp.y, xp.y);
            const float* wb = wT + kc + kk;
#pragma unroll
            for (int h = 0; h < 4; h++) {
                int gh = hbase + h;                                   // warp-uniform
                ulonglong2 w1p = *(const ulonglong2*)(wb + gh * NF);
                ulonglong2 wvp = *(const ulonglong2*)(wb + (NH + gh) * NF);
                ulonglong2 w2p = *(const ulonglong2*)(wb + (2 * NH + gh) * NF);
                FMA2(a1[h], xp.x, w1p.x); FMA2(a1[h], xp.y, w1p.y);
                FMA2(av[h], xp.x, wvp.x); FMA2(av[h], xp.y, wvp.y);
                FMA2(a2[h], sA,   w2p.x); FMA2(a2[h], sB,   w2p.y);
            }
        }
    }

    int node = nb + nrow;
    if (node < n) {
        float s1o[4], xro[4];
#pragma unroll
        for (int h = 0; h < 4; h++) {
            int gh = hbase + h;
            float l0, l1;
            UNPACK2(l0, l1, a1[h]); s1o[h] = l0 + l1;
            UNPACK2(l0, l1, av[h]); float xv   = l0 + l1;
            UNPACK2(l0, l1, a2[h]); float x2v2 = l0 + l1;
            float r = 0.5f * (xv * xv - x2v2);
            r = r > 0.f ? r : 0.f;
            xro[h] = gamma[gh] * r + beta[gh];
        }
        *(float4*)(g_s1 + (size_t)node * NH + hbase) = make_float4(s1o[0], s1o[1], s1o[2], s1o[3]);
        *(float4*)(g_xr + (size_t)node * NH + hbase) = make_float4(xro[0], xro[1], xro[2], xro[3]);
    }
}

// =====================================================================
// launch 4: scatter edges into CSR order
// =====================================================================
__global__ void k_scatter(const int* __restrict__ rows, const int* __restrict__ cols,
                          const float* __restrict__ vals, int e) {
    int i = blockIdx.x * blockDim.x + threadIdx.x;
    if (i >= e) return;
    int r = rows[i];
    int pos = atomicAdd(&g_cur[r], 1);
    u64 p = ((u64)__float_as_uint(vals[i]) << 32) | (unsigned int)cols[i];
    g_ep[pos] = p;
}

// =====================================================================
// launch 5: pull-SpMM #1 fused with bias/relu/merge/h@W2
// =====================================================================
__global__ void __launch_bounds__(256) k_spmm1mid(
    const float* __restrict__ b1, const float* __restrict__ W2, int n)
{
    __shared__ float w2s[NH * NC];
    __shared__ float b1s[NH];
    int t = threadIdx.x;
    if (t < NH * NC) w2s[t] = W2[t];
    if (t < NH)      b1s[t] = b1[t];
    __syncthreads();

    int j   = t & 7;
    int grp = t >> 3;
    int r   = blockIdx.x * 32 + grp;
    bool valid = r < n;
    int rc = valid ? r : (n - 1);
    int start = g_offs[rc];
    int end   = start + g_cnt[rc];

    float acc = 0.f, accB = 0.f;
    int i = start;
    for (; i + 2 <= end; i += 2) {
        u64 p0 = g_ep[i], p1 = g_ep[i + 1];
        int   c0 = (int)(unsigned)p0,  c1 = (int)(unsigned)p1;
        float v0 = __uint_as_float((unsigned)(p0 >> 32));
        float v1 = __uint_as_float((unsigned)(p1 >> 32));
        acc  = fmaf(v0, g_s1[(size_t)c0 * NH + j], acc);
        accB = fmaf(v1, g_s1[(size_t)c1 * NH + j], accB);
    }
    if (i < end) {
        u64 p0 = g_ep[i];
        float v0 = __uint_as_float((unsigned)(p0 >> 32));
        acc = fmaf(v0, g_s1[(size_t)((int)(unsigned)p0) * NH + j], acc);
    }
    acc += accB;

    float l = acc + b1s[j];
    l = l > 0.f ? l : 0.f;
    float h = 0.5f * (l + (valid ? g_xr[(size_t)r * NH + j] : 0.f));

    float o0 = 0.f, o1 = 0.f;
#pragma unroll
    for (int jj = 0; jj < 8; jj++) {
        float hv = __shfl_sync(0xffffffffu, h, jj, 8);
        o0 = fmaf(hv, w2s[jj * NC + j],     o0);
        o1 = fmaf(hv, w2s[jj * NC + j + 8], o1);
    }
    if (valid) {
        g_s2[(size_t)r * NC + j]     = o0;
        g_s2[(size_t)r * NC + j + 8] = o1;
    }
}

// =====================================================================
// launch 6: pull-SpMM #2 fused with +b2 and log_softmax
// =====================================================================
__global__ void __launch_bounds__(256) k_spmm2lsm(
    const float* __restrict__ b2, float* __restrict__ out, int n)
{
    __shared__ float b2s[NC];
    int t = threadIdx.x;
    if (t < NC) b2s[t] = b2[t];
    __syncthreads();

    int c   = t & 15;
    int grp = t >> 4;
    int r   = blockIdx.x * 16 + grp;
    bool valid = r < n;
    int rc = valid ? r : (n - 1);
    int start = g_offs[rc];
    int end   = start + g_cnt[rc];

    float acc = 0.f, accB = 0.f;
    int i = start;
    for (; i + 2 <= end; i += 2) {
        u64 p0 = g_ep[i], p1 = g_ep[i + 1];
        int   c0 = (int)(unsigned)p0,  c1 = (int)(unsigned)p1;
        float v0 = __uint_as_float((unsigned)(p0 >> 32));
        float v1 = __uint_as_float((unsigned)(p1 >> 32));
        acc  = fmaf(v0, g_s2[(size_t)c0 * NC + c], acc);
        accB = fmaf(v1, g_s2[(size_t)c1 * NC + c], accB);
    }
    if (i < end) {
        u64 p0 = g_ep[i];
        float v0 = __uint_as_float((unsigned)(p0 >> 32));
        acc = fmaf(v0, g_s2[(size_t)((int)(unsigned)p0) * NC + c], acc);
    }
    float v = acc + accB + b2s[c];

    float m = v;
#pragma unroll
    for (int d = 8; d; d >>= 1) m = fmaxf(m, __shfl_xor_sync(~0u, m, d, 16));
    float s = __expf(v - m);
#pragma unroll
    for (int d = 8; d; d >>= 1) s += __shfl_xor_sync(~0u, s, d, 16);
    if (valid) out[(size_t)r * NC + c] = v - m - __logf(s);
}

// ---------------- launcher -------------------------------------------
extern "C" void kernel_launch(void* const* d_in, const int* in_sizes, int n_in,
                              void* d_out, int out_size)
{
    const float* x     = (const float*)d_in[0];
    const int*   rows  = (const int*)d_in[1];
    const int*   cols  = (const int*)d_in[2];
    const float* vals  = (const float*)d_in[3];
    const float* W1    = (const float*)d_in[4];
    const float* b1    = (const float*)d_in[5];
    const float* W2    = (const float*)d_in[6];
    const float* b2    = (const float*)d_in[7];
    const float* V     = (const float*)d_in[8];
    const float* gamma = (const float*)d_in[9];
    const float* beta  = (const float*)d_in[10];
    float* out = (float*)d_out;

    int n = in_sizes[0] / NF;   // 100000
    int e = in_sizes[1];        // 3200000

    int smem = (3 * NH * NF + XTILE * XPITCH) * (int)sizeof(float);   // 59392 B
    cudaFuncSetAttribute(k_gemmA_v8, cudaFuncAttributeMaxDynamicSharedMemorySize, smem);

    // launch 0-2: CSR skeleton
    k_zero<<<(n + 1023) / 1024, 256>>>(n);
    k_hist<<<(e + 255) / 256, 256>>>(rows, e);
    k_alloc<<<(n + 1023) / 1024, 256>>>(n);

    // launch 3 (profiled slot): fused input GEMM v8 (warp h-split, 24 warps/SM)
    int nblk = (n + XTILE - 1) / XTILE;   // 782
    k_gemmA_v8<<<nblk, 256, smem>>>(x, W1, V, gamma, beta, n);

    // launch 4: scatter edges into CSR order
    k_scatter<<<(e + 255) / 256, 256>>>(rows, cols, vals, e);

    // launch 5: pull SpMM 1 + mid fusion
    k_spmm1mid<<<(n + 31) / 32, 256>>>(b1, W2, n);

    // launch 6: pull SpMM 2 + bias + log_softmax
    k_spmm2lsm<<<(n + 15) / 16, 256>>>(b2, out, n);
}

// round 16
// speedup vs baseline: 1.4792x; 1.4792x over previous
#include <cuda_runtime.h>
#include <cuda_bf16.h>
#include <cstdint>

#define NMAX  100000
#define EMAX  3200000
#define NF    512
#define NH    8
#define NC    16

// ---------------- scratch (no allocations allowed) ----------------
__device__ float g_s1[NMAX * NH];
__device__ float g_xr[NMAX * NH];
__device__ float g_s2[NMAX * NC];
__device__ int   g_cnt[NMAX];
__device__ int   g_offs[NMAX];
__device__ int   g_cur[NMAX];
__device__ int   g_total;
__device__ unsigned long long g_ep[EMAX];
// prepacked B fragments: [32 ksteps][6 frags][32 lanes] of {b0,b1}
// frag order: 0=xv_hi(n0-7) 1=xv_hi(n8-15) 2=xv_lo(n0-7) 3=xv_lo(n8-15) 4=v2_hi 5=v2_lo
__device__ uint2 g_bw[32 * 6 * 32];

typedef unsigned long long u64;

// ---------------- bf16 split + mma helpers ---------------------------
// pack {lo16=bf16(f0), hi16=bf16(f1)} and the residual-lo pack
__device__ __forceinline__ void split2(float f0, float f1, uint32_t& hi, uint32_t& lo) {
    uint32_t h;
    asm("cvt.rn.bf16x2.f32 %0, %1, %2;" : "=r"(h) : "f"(f1), "f"(f0));
    float h0 = __uint_as_float(h << 16);
    float h1 = __uint_as_float(h & 0xFFFF0000u);
    float l0 = f0 - h0, l1 = f1 - h1;
    asm("cvt.rn.bf16x2.f32 %0, %1, %2;" : "=r"(lo) : "f"(l1), "f"(l0));
    hi = h;
}

__device__ __forceinline__ void mma16816(float d[4], const uint32_t a[4], uint32_t b0, uint32_t b1) {
    asm volatile(
        "mma.sync.aligned.m16n8k16.row.col.f32.bf16.bf16.f32 "
        "{%0,%1,%2,%3}, {%4,%5,%6,%7}, {%8,%9}, {%0,%1,%2,%3};"
        : "+f"(d[0]), "+f"(d[1]), "+f"(d[2]), "+f"(d[3])
        : "r"(a[0]), "r"(a[1]), "r"(a[2]), "r"(a[3]), "r"(b0), "r"(b1));
}

// =====================================================================
// launch 0: zero counters
// =====================================================================
__global__ void k_zero(int n) {
    int i = blockIdx.x * blockDim.x + threadIdx.x;
    int i4 = i * 4;
    if (i4 + 3 < n) {
        *(int4*)(g_cnt + i4) = make_int4(0, 0, 0, 0);
    } else {
        for (int q = 0; q < 4; q++) if (i4 + q < n) g_cnt[i4 + q] = 0;
    }
    if (i == 0) g_total = 0;
}

// =====================================================================
// launch 1: degree histogram
// =====================================================================
__global__ void k_hist(const int* __restrict__ rows, int e) {
    int i = blockIdx.x * blockDim.x + threadIdx.x;
    if (i < e) atomicAdd(&g_cnt[rows[i]], 1);
}

// =====================================================================
// launch 2: prepack B fragments (bf16 hi/lo, mma.m16n8k16 col-major B)
// B reg j holds k-rows tig*2 + j*8 + {0,1}, n-col = g  (g=lane>>2, tig=lane&3)
// =====================================================================
__global__ void k_prepB(const float* __restrict__ W1, const float* __restrict__ V) {
    int i = blockIdx.x * blockDim.x + threadIdx.x;
    if (i >= 32 * 6 * 32) return;
    int lane = i & 31;
    int f    = (i >> 5) % 6;
    int ks   = i / (6 * 32);
    int g = lane >> 2, tig = lane & 3;
    bool want_lo = (f == 2 || f == 3 || f == 5);
    uint32_t r[2];
#pragma unroll
    for (int j = 0; j < 2; j++) {
        int k0 = ks * 16 + tig * 2 + j * 8;
        float w0, w1;
        if (f == 0 || f == 2) {            // W1 col g
            w0 = W1[k0 * NH + g]; w1 = W1[(k0 + 1) * NH + g];
        } else if (f == 1 || f == 3) {     // V col g
            w0 = V[k0 * NH + g];  w1 = V[(k0 + 1) * NH + g];
        } else {                           // V^2 col g
            float a = V[k0 * NH + g], b = V[(k0 + 1) * NH + g];
            w0 = a * a; w1 = b * b;
        }
        uint32_t hi, lo;
        split2(w0, w1, hi, lo);
        r[j] = want_lo ? lo : hi;
    }
    g_bw[(ks * 6 + f) * 32 + lane] = make_uint2(r[0], r[1]);
}

// =====================================================================
// launch 3 (PROFILED SLOT): gemmA via mma.sync bf16 split precision
// Block = 256 threads = 8 warps = 256 nodes (2 m16-tiles per warp).
// No smem. A frags built in registers from coalesced LDG of x.
//   D_xv[.,0:8]=x@W1, D_xv[.,8:16]=x@V, D_x2[.,0:8]=x^2@V^2, fp32 accum.
// =====================================================================
__global__ void __launch_bounds__(256) k_gemmA_mma(
    const float* __restrict__ x, const float* __restrict__ gamma,
    const float* __restrict__ beta, int n)
{
    const int t    = threadIdx.x;
    const int w    = t >> 5;
    const int lane = t & 31;
    const int g    = lane >> 2;
    const int tig  = lane & 3;
    const int nb   = blockIdx.x * 256;
    const int m0   = nb + w * 32;          // warp's 32-node range

    float dxv0[2][4], dxv1[2][4], dx2[2][4];
#pragma unroll
    for (int tt = 0; tt < 2; tt++)
#pragma unroll
        for (int q = 0; q < 4; q++) { dxv0[tt][q] = 0.f; dxv1[tt][q] = 0.f; dx2[tt][q] = 0.f; }

#pragma unroll 1
    for (int ks = 0; ks < 32; ks++) {
        const int kb = ks * 16;
        // B frags (broadcast across warps -> L1 hits)
        uint2 bf0 = __ldg(&g_bw[(ks * 6 + 0) * 32 + lane]);
        uint2 bf1 = __ldg(&g_bw[(ks * 6 + 1) * 32 + lane]);
        uint2 bf2 = __ldg(&g_bw[(ks * 6 + 2) * 32 + lane]);
        uint2 bf3 = __ldg(&g_bw[(ks * 6 + 3) * 32 + lane]);
        uint2 bf4 = __ldg(&g_bw[(ks * 6 + 4) * 32 + lane]);
        uint2 bf5 = __ldg(&g_bw[(ks * 6 + 5) * 32 + lane]);

#pragma unroll
        for (int tt = 0; tt < 2; tt++) {
            int row0 = m0 + tt * 16 + g;
            int row1 = row0 + 8;
            float2 z = make_float2(0.f, 0.f);
            float2 p00 = z, p10 = z, p01 = z, p11 = z;
            if (row0 < n) {
                p00 = *(const float2*)(x + (size_t)row0 * NF + kb + tig * 2);
                p01 = *(const float2*)(x + (size_t)row0 * NF + kb + tig * 2 + 8);
            }
            if (row1 < n) {
                p10 = *(const float2*)(x + (size_t)row1 * NF + kb + tig * 2);
                p11 = *(const float2*)(x + (size_t)row1 * NF + kb + tig * 2 + 8);
            }
            // A fragments: a0=(g,c) a1=(g+8,c) a2=(g,c+8) a3=(g+8,c+8)
            uint32_t axh[4], axl[4], ash[4], asl[4];
            split2(p00.x, p00.y, axh[0], axl[0]);
            split2(p10.x, p10.y, axh[1], axl[1]);
            split2(p01.x, p01.y, axh[2], axl[2]);
            split2(p11.x, p11.y, axh[3], axl[3]);
            split2(p00.x * p00.x, p00.y * p00.y, ash[0], asl[0]);
            split2(p10.x * p10.x, p10.y * p10.y, ash[1], asl[1]);
            split2(p01.x * p01.x, p01.y * p01.y, ash[2], asl[2]);
            split2(p11.x * p11.x, p11.y * p11.y, ash[3], asl[3]);

            // D_xv n0-7: hihi + hilo + lohi
            mma16816(dxv0[tt], axh, bf0.x, bf0.y);
            mma16816(dxv0[tt], axh, bf2.x, bf2.y);
            mma16816(dxv0[tt], axl, bf0.x, bf0.y);
            // D_xv n8-15
            mma16816(dxv1[tt], axh, bf1.x, bf1.y);
            mma16816(dxv1[tt], axh, bf3.x, bf3.y);
            mma16816(dxv1[tt], axl, bf1.x, bf1.y);
            // D_x2 n0-7
            mma16816(dx2[tt], ash, bf4.x, bf4.y);
            mma16816(dx2[tt], ash, bf5.x, bf5.y);
            mma16816(dx2[tt], asl, bf4.x, bf4.y);
        }
    }

    // epilogue: d0,d1=(row g, h=tig*2,tig*2+1); d2,d3=(row g+8, same h)
    float ga0 = gamma[tig * 2], ga1 = gamma[tig * 2 + 1];
    float be0 = beta[tig * 2],  be1 = beta[tig * 2 + 1];
#pragma unroll
    for (int tt = 0; tt < 2; tt++) {
#pragma unroll
        for (int rs = 0; rs < 2; rs++) {
            int node = m0 + tt * 16 + g + rs * 8;
            if (node < n) {
                float s1a = dxv0[tt][rs * 2 + 0], s1b = dxv0[tt][rs * 2 + 1];
                float xva = dxv1[tt][rs * 2 + 0], xvb = dxv1[tt][rs * 2 + 1];
                float x2a = dx2[tt][rs * 2 + 0],  x2b = dx2[tt][rs * 2 + 1];
                float ra = 0.5f * (xva * xva - x2a); ra = ra > 0.f ? ra : 0.f;
                float rb = 0.5f * (xvb * xvb - x2b); rb = rb > 0.f ? rb : 0.f;
                *(float2*)(g_s1 + (size_t)node * NH + tig * 2) = make_float2(s1a, s1b);
                *(float2*)(g_xr + (size_t)node * NH + tig * 2) =
                    make_float2(ga0 * ra + be0, ga1 * rb + be1);
            }
        }
    }
}

// =====================================================================
// launch 4: allocate contiguous per-row ranges (block scan + 1 atomic/block)
// =====================================================================
__global__ void __launch_bounds__(256) k_alloc(int n) {
    __shared__ int wsum[8];
    __shared__ int wpref[8];
    __shared__ int blockBase;
    int t = threadIdx.x;
    int lane = t & 31, wid = t >> 5;
    int base = blockIdx.x * 1024 + t * 4;

    int v[4]; int s = 0;
#pragma unroll
    for (int q = 0; q < 4; q++) { int i = base + q; v[q] = (i < n) ? g_cnt[i] : 0; s += v[q]; }

    int sc = s;
#pragma unroll
    for (int d = 1; d < 32; d <<= 1) {
        int u = __shfl_up_sync(~0u, sc, d);
        if (lane >= d) sc += u;
    }
    if (lane == 31) wsum[wid] = sc;
    __syncthreads();
    if (t == 0) {
        int run = 0;
#pragma unroll
        for (int w2 = 0; w2 < 8; w2++) { wpref[w2] = run; run += wsum[w2]; }
        blockBase = atomicAdd(&g_total, run);
    }
    __syncthreads();

    int run = blockBase + wpref[wid] + (sc - s);
#pragma unroll
    for (int q = 0; q < 4; q++) {
        int i = base + q;
        if (i < n) {
            g_offs[i] = run;
            g_cur[i]  = run;
            run += v[q];
        }
    }
}

// =====================================================================
// launch 5: scatter edges into CSR order
// =====================================================================
__global__ void k_scatter(const int* __restrict__ rows, const int* __restrict__ cols,
                          const float* __restrict__ vals, int e) {
    int i = blockIdx.x * blockDim.x + threadIdx.x;
    if (i >= e) return;
    int r = rows[i];
    int pos = atomicAdd(&g_cur[r], 1);
    u64 p = ((u64)__float_as_uint(vals[i]) << 32) | (unsigned int)cols[i];
    g_ep[pos] = p;
}

// =====================================================================
// launch 6: pull-SpMM #1 fused with bias/relu/merge/h@W2
// =====================================================================
__global__ void __launch_bounds__(256) k_spmm1mid(
    const float* __restrict__ b1, const float* __restrict__ W2, int n)
{
    __shared__ float w2s[NH * NC];
    __shared__ float b1s[NH];
    int t = threadIdx.x;
    if (t < NH * NC) w2s[t] = W2[t];
    if (t < NH)      b1s[t] = b1[t];
    __syncthreads();

    int j   = t & 7;
    int grp = t >> 3;
    int r   = blockIdx.x * 32 + grp;
    bool valid = r < n;
    int rc = valid ? r : (n - 1);
    int start = g_offs[rc];
    int end   = start + g_cnt[rc];

    float acc = 0.f, accB = 0.f;
    int i = start;
    for (; i + 2 <= end; i += 2) {
        u64 p0 = g_ep[i], p1 = g_ep[i + 1];
        int   c0 = (int)(unsigned)p0,  c1 = (int)(unsigned)p1;
        float v0 = __uint_as_float((unsigned)(p0 >> 32));
        float v1 = __uint_as_float((unsigned)(p1 >> 32));
        acc  = fmaf(v0, g_s1[(size_t)c0 * NH + j], acc);
        accB = fmaf(v1, g_s1[(size_t)c1 * NH + j], accB);
    }
    if (i < end) {
        u64 p0 = g_ep[i];
        float v0 = __uint_as_float((unsigned)(p0 >> 32));
        acc = fmaf(v0, g_s1[(size_t)((int)(unsigned)p0) * NH + j], acc);
    }
    acc += accB;

    float l = acc + b1s[j];
    l = l > 0.f ? l : 0.f;
    float h = 0.5f * (l + (valid ? g_xr[(size_t)r * NH + j] : 0.f));

    float o0 = 0.f, o1 = 0.f;
#pragma unroll
    for (int jj = 0; jj < 8; jj++) {
        float hv = __shfl_sync(0xffffffffu, h, jj, 8);
        o0 = fmaf(hv, w2s[jj * NC + j],     o0);
        o1 = fmaf(hv, w2s[jj * NC + j + 8], o1);
    }
    if (valid) {
        g_s2[(size_t)r * NC + j]     = o0;
        g_s2[(size_t)r * NC + j + 8] = o1;
    }
}

// =====================================================================
// launch 7: pull-SpMM #2 fused with +b2 and log_softmax
// =====================================================================
__global__ void __launch_bounds__(256) k_spmm2lsm(
    const float* __restrict__ b2, float* __restrict__ out, int n)
{
    __shared__ float b2s[NC];
    int t = threadIdx.x;
    if (t < NC) b2s[t] = b2[t];
    __syncthreads();

    int c   = t & 15;
    int grp = t >> 4;
    int r   = blockIdx.x * 16 + grp;
    bool valid = r < n;
    int rc = valid ? r : (n - 1);
    int start = g_offs[rc];
    int end   = start + g_cnt[rc];

    float acc = 0.f, accB = 0.f;
    int i = start;
    for (; i + 2 <= end; i += 2) {
        u64 p0 = g_ep[i], p1 = g_ep[i + 1];
        int   c0 = (int)(unsigned)p0,  c1 = (int)(unsigned)p1;
        float v0 = __uint_as_float((unsigned)(p0 >> 32));
        float v1 = __uint_as_float((unsigned)(p1 >> 32));
        acc  = fmaf(v0, g_s2[(size_t)c0 * NC + c], acc);
        accB = fmaf(v1, g_s2[(size_t)c1 * NC + c], accB);
    }
    if (i < end) {
        u64 p0 = g_ep[i];
        float v0 = __uint_as_float((unsigned)(p0 >> 32));
        acc = fmaf(v0, g_s2[(size_t)((int)(unsigned)p0) * NC + c], acc);
    }
    float v = acc + accB + b2s[c];

    float m = v;
#pragma unroll
    for (int d = 8; d; d >>= 1) m = fmaxf(m, __shfl_xor_sync(~0u, m, d, 16));
    float s = __expf(v - m);
#pragma unroll
    for (int d = 8; d; d >>= 1) s += __shfl_xor_sync(~0u, s, d, 16);
    if (valid) out[(size_t)r * NC + c] = v - m - __logf(s);
}

// ---------------- launcher -------------------------------------------
extern "C" void kernel_launch(void* const* d_in, const int* in_sizes, int n_in,
                              void* d_out, int out_size)
{
    const float* x     = (const float*)d_in[0];
    const int*   rows  = (const int*)d_in[1];
    const int*   cols  = (const int*)d_in[2];
    const float* vals  = (const float*)d_in[3];
    const float* W1    = (const float*)d_in[4];
    const float* b1    = (const float*)d_in[5];
    const float* W2    = (const float*)d_in[6];
    const float* b2    = (const float*)d_in[7];
    const float* V     = (const float*)d_in[8];
    const float* gamma = (const float*)d_in[9];
    const float* beta  = (const float*)d_in[10];
    float* out = (float*)d_out;

    int n = in_sizes[0] / NF;   // 100000
    int e = in_sizes[1];        // 3200000

    // launch 0-2: CSR counters + B fragment prepack
    k_zero<<<(n + 1023) / 1024, 256>>>(n);
    k_hist<<<(e + 255) / 256, 256>>>(rows, e);
    k_prepB<<<(32 * 6 * 32 + 255) / 256, 256>>>(W1, V);

    // launch 3 (profiled slot): tensor-core (mma.sync) gemmA
    int nblk = (n + 255) / 256;   // 391
    k_gemmA_mma<<<nblk, 256>>>(x, gamma, beta, n);

    // launch 4: allocate CSR ranges
    k_alloc<<<(n + 1023) / 1024, 256>>>(n);

    // launch 5: scatter edges into CSR order
    k_scatter<<<(e + 255) / 256, 256>>>(rows, cols, vals, e);

    // launch 6: pull SpMM 1 + mid fusion
    k_spmm1mid<<<(n + 31) / 32, 256>>>(b1, W2, n);

    // launch 7: pull SpMM 2 + bias + log_softmax
    k_spmm2lsm<<<(n + 15) / 16, 256>>>(b2, out, n);
}